// round 2
// baseline (speedup 1.0000x reference)
#include <cuda_runtime.h>
#include <cstdint>

// LabelwiseAttention: B=4, S=4096, D=256, C=8921
//   scores[b,c,s] = sum_d x[b,s,d] * W[c,d]
//   attn          = softmax_s(scores)
//   logits[b,c,d] = sum_s attn[b,c,s] * x[b,s,d]
// d_out = [logits (B*C*D) | attention (B*C*S)], fp32.

#define B_ 4
#define S_ 4096
#define D_ 256
#define C_ 8921

// ---------------------------------------------------------------------------
// GEMM1: scores (attention scratch) = W[C,D] @ x_b[S,D]^T  per batch
// block tile 128(m=c) x 128(n=s), K-chunk 16, 256 threads, 8x8 micro tile
// ---------------------------------------------------------------------------
__global__ __launch_bounds__(256) void gemm_scores_kernel(
    const float* __restrict__ x, const float* __restrict__ W,
    float* __restrict__ scores)
{
    __shared__ float As[16][128];  // [k][m]  (from W)
    __shared__ float Bs[16][128];  // [k][n]  (from x)

    const int b  = blockIdx.z;
    const int m0 = blockIdx.y * 128;   // c tile
    const int n0 = blockIdx.x * 128;   // s tile
    const float* xb = x + (size_t)b * S_ * D_;

    const int tid = threadIdx.x;
    const int tx = tid & 15;   // n direction
    const int ty = tid >> 4;   // m direction

    float acc[8][8];
    #pragma unroll
    for (int i = 0; i < 8; i++)
        #pragma unroll
        for (int j = 0; j < 8; j++) acc[i][j] = 0.f;

    for (int kc = 0; kc < D_; kc += 16) {
        // load A tile (W rows = c), transpose to As[k][m]
        #pragma unroll
        for (int i = 0; i < 2; i++) {
            int f   = tid + i * 256;      // 0..511 float4 slots
            int row = f >> 2;             // 0..127
            int col = (f & 3) * 4;        // 0,4,8,12
            int c   = m0 + row;
            float4 v = make_float4(0.f, 0.f, 0.f, 0.f);
            if (c < C_) v = *(const float4*)(W + (size_t)c * D_ + kc + col);
            As[col + 0][row] = v.x;
            As[col + 1][row] = v.y;
            As[col + 2][row] = v.z;
            As[col + 3][row] = v.w;
        }
        // load B tile (x rows = s), transpose to Bs[k][n]. S divisible by 128.
        #pragma unroll
        for (int i = 0; i < 2; i++) {
            int f   = tid + i * 256;
            int row = f >> 2;
            int col = (f & 3) * 4;
            float4 v = *(const float4*)(xb + (size_t)(n0 + row) * D_ + kc + col);
            Bs[col + 0][row] = v.x;
            Bs[col + 1][row] = v.y;
            Bs[col + 2][row] = v.z;
            Bs[col + 3][row] = v.w;
        }
        __syncthreads();

        #pragma unroll
        for (int k = 0; k < 16; k++) {
            float a[8], bb[8];
            *(float4*)&a[0]  = *(const float4*)&As[k][ty * 8];
            *(float4*)&a[4]  = *(const float4*)&As[k][ty * 8 + 4];
            *(float4*)&bb[0] = *(const float4*)&Bs[k][tx * 8];
            *(float4*)&bb[4] = *(const float4*)&Bs[k][tx * 8 + 4];
            #pragma unroll
            for (int i = 0; i < 8; i++)
                #pragma unroll
                for (int j = 0; j < 8; j++)
                    acc[i][j] += a[i] * bb[j];
        }
        __syncthreads();
    }

    // store scores[b, c, s]
    float* outb = scores + (size_t)b * C_ * S_;
    #pragma unroll
    for (int i = 0; i < 8; i++) {
        int c = m0 + ty * 8 + i;
        if (c >= C_) break;  // rows are monotonically increasing
        float* rp = outb + (size_t)c * S_ + n0 + tx * 8;
        float4 v0 = make_float4(acc[i][0], acc[i][1], acc[i][2], acc[i][3]);
        float4 v1 = make_float4(acc[i][4], acc[i][5], acc[i][6], acc[i][7]);
        *(float4*)(rp)     = v0;
        *(float4*)(rp + 4) = v1;
    }
}

// ---------------------------------------------------------------------------
// Softmax over S=4096 per (b,c) row, in place. One block (256 thr) per row.
// 16 values per thread held in registers (single global read + write).
// ---------------------------------------------------------------------------
__global__ __launch_bounds__(256) void softmax_rows_kernel(float* __restrict__ attn)
{
    float* p = attn + (size_t)blockIdx.x * S_;
    const int tid = threadIdx.x;

    float4 v[4];
    float m = -3.402823466e38f;
    #pragma unroll
    for (int i = 0; i < 4; i++) {
        v[i] = *(const float4*)(p + (size_t)(tid + i * 256) * 4);
        m = fmaxf(m, fmaxf(fmaxf(v[i].x, v[i].y), fmaxf(v[i].z, v[i].w)));
    }

    __shared__ float red[8];
    #pragma unroll
    for (int o = 16; o; o >>= 1) m = fmaxf(m, __shfl_xor_sync(0xFFFFFFFFu, m, o));
    if ((tid & 31) == 0) red[tid >> 5] = m;
    __syncthreads();
    if (tid < 32) {
        float t = (tid < 8) ? red[tid] : -3.402823466e38f;
        #pragma unroll
        for (int o = 4; o; o >>= 1) t = fmaxf(t, __shfl_xor_sync(0xFFFFFFFFu, t, o));
        if (tid == 0) red[0] = t;
    }
    __syncthreads();
    m = red[0];
    __syncthreads();

    float s = 0.f;
    #pragma unroll
    for (int i = 0; i < 4; i++) {
        v[i].x = expf(v[i].x - m);
        v[i].y = expf(v[i].y - m);
        v[i].z = expf(v[i].z - m);
        v[i].w = expf(v[i].w - m);
        s += (v[i].x + v[i].y) + (v[i].z + v[i].w);
    }
    #pragma unroll
    for (int o = 16; o; o >>= 1) s += __shfl_xor_sync(0xFFFFFFFFu, s, o);
    if ((tid & 31) == 0) red[tid >> 5] = s;
    __syncthreads();
    if (tid < 32) {
        float t = (tid < 8) ? red[tid] : 0.f;
        #pragma unroll
        for (int o = 4; o; o >>= 1) t += __shfl_xor_sync(0xFFFFFFFFu, t, o);
        if (tid == 0) red[0] = t;
    }
    __syncthreads();
    const float inv = 1.0f / red[0];

    #pragma unroll
    for (int i = 0; i < 4; i++) {
        float4 o4 = make_float4(v[i].x * inv, v[i].y * inv, v[i].z * inv, v[i].w * inv);
        *(float4*)(p + (size_t)(tid + i * 256) * 4) = o4;
    }
}

// ---------------------------------------------------------------------------
// GEMM2: logits = attn[C,S] @ x_b[S,D]  per batch
// block tile 128(m=c) x 128(n=d), K-chunk 16 over S, 256 threads, 8x8 micro
// ---------------------------------------------------------------------------
__global__ __launch_bounds__(256) void gemm_logits_kernel(
    const float* __restrict__ x, const float* __restrict__ attn,
    float* __restrict__ logits)
{
    __shared__ float As[16][128];  // [k][m]  (from attn, transposed)
    __shared__ float Bs[16][128];  // [k][n]  (from x, natural)

    const int b  = blockIdx.z;
    const int m0 = blockIdx.y * 128;   // c tile
    const int n0 = blockIdx.x * 128;   // d tile (2 tiles)
    const float* Ab = attn + (size_t)b * C_ * S_;
    const float* xb = x + (size_t)b * S_ * D_;

    const int tid = threadIdx.x;
    const int tx = tid & 15;
    const int ty = tid >> 4;

    float acc[8][8];
    #pragma unroll
    for (int i = 0; i < 8; i++)
        #pragma unroll
        for (int j = 0; j < 8; j++) acc[i][j] = 0.f;

    for (int kc = 0; kc < S_; kc += 16) {
        // A tile: attn rows c = m0+row, cols kc..kc+15 (row length S_)
        #pragma unroll
        for (int i = 0; i < 2; i++) {
            int f   = tid + i * 256;
            int row = f >> 2;
            int col = (f & 3) * 4;
            int c   = m0 + row;
            float4 v = make_float4(0.f, 0.f, 0.f, 0.f);
            if (c < C_) v = *(const float4*)(Ab + (size_t)c * S_ + kc + col);
            As[col + 0][row] = v.x;
            As[col + 1][row] = v.y;
            As[col + 2][row] = v.z;
            As[col + 3][row] = v.w;
        }
        // B tile: x rows kc+krow, cols n0..n0+127 (row length D_=256), natural layout
        #pragma unroll
        for (int i = 0; i < 2; i++) {
            int f    = tid + i * 256;
            int krow = f >> 5;            // 0..15
            int ncol = (f & 31) * 4;      // 0..124
            float4 v = *(const float4*)(xb + (size_t)(kc + krow) * D_ + n0 + ncol);
            *(float4*)&Bs[krow][ncol] = v;
        }
        __syncthreads();

        #pragma unroll
        for (int k = 0; k < 16; k++) {
            float a[8], bb[8];
            *(float4*)&a[0]  = *(const float4*)&As[k][ty * 8];
            *(float4*)&a[4]  = *(const float4*)&As[k][ty * 8 + 4];
            *(float4*)&bb[0] = *(const float4*)&Bs[k][tx * 8];
            *(float4*)&bb[4] = *(const float4*)&Bs[k][tx * 8 + 4];
            #pragma unroll
            for (int i = 0; i < 8; i++)
                #pragma unroll
                for (int j = 0; j < 8; j++)
                    acc[i][j] += a[i] * bb[j];
        }
        __syncthreads();
    }

    // store logits[b, c, d]
    float* outb = logits + (size_t)b * C_ * D_;
    #pragma unroll
    for (int i = 0; i < 8; i++) {
        int c = m0 + ty * 8 + i;
        if (c >= C_) break;
        float* rp = outb + (size_t)c * D_ + n0 + tx * 8;
        float4 v0 = make_float4(acc[i][0], acc[i][1], acc[i][2], acc[i][3]);
        float4 v1 = make_float4(acc[i][4], acc[i][5], acc[i][6], acc[i][7]);
        *(float4*)(rp)     = v0;
        *(float4*)(rp + 4) = v1;
    }
}

// ---------------------------------------------------------------------------
extern "C" void kernel_launch(void* const* d_in, const int* in_sizes, int n_in,
                              void* d_out, int out_size)
{
    const float* x = (const float*)d_in[0];   // [B, S, D]
    const float* W = (const float*)d_in[1];   // [C, D]

    float* logits = (float*)d_out;                            // [B, C, D]
    float* attn   = (float*)d_out + (size_t)B_ * C_ * D_;     // [B, C, S]

    dim3 g1(S_ / 128, (C_ + 127) / 128, B_);
    gemm_scores_kernel<<<g1, 256>>>(x, W, attn);

    softmax_rows_kernel<<<B_ * C_, 256>>>(attn);

    dim3 g3(D_ / 128, (C_ + 127) / 128, B_);
    gemm_logits_kernel<<<g3, 256>>>(x, attn, logits);
}

// round 4
// speedup vs baseline: 2.3956x; 2.3956x over previous
#include <cuda_runtime.h>
#include <cuda_bf16.h>
#include <cstdint>

// LabelwiseAttention: B=4, S=4096, D=256, C=8921
//   scores[b,c,s] = sum_d x[b,s,d] * W[c,d]
//   attn          = softmax_s(scores)
//   logits[b,c,d] = sum_s attn[b,c,s] * x[b,s,d]
// d_out = [logits (B*C*D) | attention (B*C*S)], fp32.
//
// GEMMs run on tensor cores via bf16 hi/lo split (3 mma terms):
//   A*B ~= Ah*Bh + Ah*Bl + Al*Bh   (error ~2^-18 per element, fp32 accum)

#define B_ 4
#define S_ 4096
#define D_ 256
#define C_ 8921

#define PADA 24    // b16 row stride for [row][16] tiles (conflict-free ldmatrix)
#define PADB2 136  // b16 row stride for gemm2 B tiles [16][128]

// ---------------------------------------------------------------------------
// helpers
// ---------------------------------------------------------------------------
__device__ __forceinline__ void split_store4(float4 v, __nv_bfloat16* ph, __nv_bfloat16* pl)
{
    __nv_bfloat16 h0 = __float2bfloat16_rn(v.x);
    __nv_bfloat16 h1 = __float2bfloat16_rn(v.y);
    __nv_bfloat16 h2 = __float2bfloat16_rn(v.z);
    __nv_bfloat16 h3 = __float2bfloat16_rn(v.w);
    __nv_bfloat16 l0 = __float2bfloat16_rn(v.x - __bfloat162float(h0));
    __nv_bfloat16 l1 = __float2bfloat16_rn(v.y - __bfloat162float(h1));
    __nv_bfloat16 l2 = __float2bfloat16_rn(v.z - __bfloat162float(h2));
    __nv_bfloat16 l3 = __float2bfloat16_rn(v.w - __bfloat162float(h3));
    ((__nv_bfloat162*)ph)[0] = __halves2bfloat162(h0, h1);
    ((__nv_bfloat162*)ph)[1] = __halves2bfloat162(h2, h3);
    ((__nv_bfloat162*)pl)[0] = __halves2bfloat162(l0, l1);
    ((__nv_bfloat162*)pl)[1] = __halves2bfloat162(l2, l3);
}

__device__ __forceinline__ void ldsm_x4(uint32_t& r0, uint32_t& r1, uint32_t& r2, uint32_t& r3,
                                        uint32_t addr)
{
    asm volatile("ldmatrix.sync.aligned.m8n8.x4.shared.b16 {%0,%1,%2,%3}, [%4];\n"
                 : "=r"(r0), "=r"(r1), "=r"(r2), "=r"(r3) : "r"(addr));
}

__device__ __forceinline__ void ldsm_x4_t(uint32_t& r0, uint32_t& r1, uint32_t& r2, uint32_t& r3,
                                          uint32_t addr)
{
    asm volatile("ldmatrix.sync.aligned.m8n8.x4.trans.shared.b16 {%0,%1,%2,%3}, [%4];\n"
                 : "=r"(r0), "=r"(r1), "=r"(r2), "=r"(r3) : "r"(addr));
}

__device__ __forceinline__ void mma_bf16(float* c, const uint32_t* a, uint32_t b0, uint32_t b1)
{
    asm volatile(
        "mma.sync.aligned.m16n8k16.row.col.f32.bf16.bf16.f32 "
        "{%0,%1,%2,%3}, {%4,%5,%6,%7}, {%8,%9}, {%0,%1,%2,%3};\n"
        : "+f"(c[0]), "+f"(c[1]), "+f"(c[2]), "+f"(c[3])
        : "r"(a[0]), "r"(a[1]), "r"(a[2]), "r"(a[3]), "r"(b0), "r"(b1));
}

// ---------------------------------------------------------------------------
// GEMM1: scores[b,c,s] = W[c,:] . x[b,s,:]    block tile 128(c) x 128(s), K=D
// ---------------------------------------------------------------------------
__global__ __launch_bounds__(256) void gemm_scores_tc(
    const float* __restrict__ x, const float* __restrict__ W,
    float* __restrict__ scores)
{
    __shared__ __align__(16) __nv_bfloat16 sAh[128 * PADA];
    __shared__ __align__(16) __nv_bfloat16 sAl[128 * PADA];
    __shared__ __align__(16) __nv_bfloat16 sBh[128 * PADA];
    __shared__ __align__(16) __nv_bfloat16 sBl[128 * PADA];

    const int b  = blockIdx.z;
    const int m0 = blockIdx.y * 128;   // c
    const int n0 = blockIdx.x * 128;   // s
    const float* xb = x + (size_t)b * S_ * D_;

    const int tid  = threadIdx.x;
    const int lane = tid & 31;
    const int wid  = tid >> 5;
    const int wm   = (wid >> 2) * 64;
    const int wn   = (wid & 3) * 32;

    // ldmatrix addresses (byte offsets within arrays, lane-dependent, loop-invariant)
    const int a_r = lane & 15;
    const int a_c = (lane >> 4) * 8;
    uint32_t aAh = (uint32_t)__cvta_generic_to_shared(sAh);
    uint32_t aAl = (uint32_t)__cvta_generic_to_shared(sAl);
    uint32_t aBh = (uint32_t)__cvta_generic_to_shared(sBh);
    uint32_t aBl = (uint32_t)__cvta_generic_to_shared(sBl);
    uint32_t a_off[4], b_off[2];
    #pragma unroll
    for (int i = 0; i < 4; i++)
        a_off[i] = (uint32_t)(((wm + 16 * i + a_r) * PADA + a_c) * 2);
    #pragma unroll
    for (int j = 0; j < 2; j++) {
        int nrow = wn + (2 * j + (lane >> 4)) * 8 + (lane & 7);
        int col  = ((lane >> 3) & 1) * 8;
        b_off[j] = (uint32_t)((nrow * PADA + col) * 2);
    }

    float acc[4][4][4];
    #pragma unroll
    for (int i = 0; i < 4; i++)
        #pragma unroll
        for (int j = 0; j < 4; j++)
            #pragma unroll
            for (int k = 0; k < 4; k++) acc[i][j][k] = 0.f;

    for (int kc = 0; kc < D_; kc += 16) {
        __syncthreads();
        // A: W rows m0..m0+127, cols kc..kc+15
        #pragma unroll
        for (int i = 0; i < 2; i++) {
            int f = tid + i * 256;
            int row = f >> 2, cg = (f & 3) * 4;
            int c = m0 + row;
            float4 v = make_float4(0.f, 0.f, 0.f, 0.f);
            if (c < C_) v = *(const float4*)(W + (size_t)c * D_ + kc + cg);
            split_store4(v, &sAh[row * PADA + cg], &sAl[row * PADA + cg]);
        }
        // B: x rows n0..n0+127, cols kc..kc+15
        #pragma unroll
        for (int i = 0; i < 2; i++) {
            int f = tid + i * 256;
            int row = f >> 2, cg = (f & 3) * 4;
            float4 v = *(const float4*)(xb + (size_t)(n0 + row) * D_ + kc + cg);
            split_store4(v, &sBh[row * PADA + cg], &sBl[row * PADA + cg]);
        }
        __syncthreads();

        uint32_t Ah[4][4], Al[4][4], Bh[2][4], Bl[2][4];
        #pragma unroll
        for (int i = 0; i < 4; i++) {
            ldsm_x4(Ah[i][0], Ah[i][1], Ah[i][2], Ah[i][3], aAh + a_off[i]);
            ldsm_x4(Al[i][0], Al[i][1], Al[i][2], Al[i][3], aAl + a_off[i]);
        }
        #pragma unroll
        for (int j = 0; j < 2; j++) {
            ldsm_x4(Bh[j][0], Bh[j][1], Bh[j][2], Bh[j][3], aBh + b_off[j]);
            ldsm_x4(Bl[j][0], Bl[j][1], Bl[j][2], Bl[j][3], aBl + b_off[j]);
        }

        #pragma unroll
        for (int mi = 0; mi < 4; mi++)
            #pragma unroll
            for (int nj = 0; nj < 4; nj++) {
                int jp = nj >> 1, s2 = (nj & 1) * 2;
                mma_bf16(acc[mi][nj], Ah[mi], Bh[jp][s2], Bh[jp][s2 + 1]);
                mma_bf16(acc[mi][nj], Ah[mi], Bl[jp][s2], Bl[jp][s2 + 1]);
                mma_bf16(acc[mi][nj], Al[mi], Bh[jp][s2], Bh[jp][s2 + 1]);
            }
    }

    // epilogue
    float* outb = scores + (size_t)b * C_ * S_;
    #pragma unroll
    for (int mi = 0; mi < 4; mi++) {
        int c0r = m0 + wm + 16 * mi + (lane >> 2);
        #pragma unroll
        for (int nj = 0; nj < 4; nj++) {
            int s = n0 + wn + 8 * nj + (lane & 3) * 2;
            if (c0r < C_)
                *(float2*)(outb + (size_t)c0r * S_ + s) = make_float2(acc[mi][nj][0], acc[mi][nj][1]);
            if (c0r + 8 < C_)
                *(float2*)(outb + (size_t)(c0r + 8) * S_ + s) = make_float2(acc[mi][nj][2], acc[mi][nj][3]);
        }
    }
}

// ---------------------------------------------------------------------------
// Softmax over S=4096 per (b,c) row, in place.
// ---------------------------------------------------------------------------
__global__ __launch_bounds__(256) void softmax_rows_kernel(float* __restrict__ attn)
{
    float* p = attn + (size_t)blockIdx.x * S_;
    const int tid = threadIdx.x;

    float4 v[4];
    float m = -3.402823466e38f;
    #pragma unroll
    for (int i = 0; i < 4; i++) {
        v[i] = *(const float4*)(p + (size_t)(tid + i * 256) * 4);
        m = fmaxf(m, fmaxf(fmaxf(v[i].x, v[i].y), fmaxf(v[i].z, v[i].w)));
    }

    __shared__ float red[8];
    #pragma unroll
    for (int o = 16; o; o >>= 1) m = fmaxf(m, __shfl_xor_sync(0xFFFFFFFFu, m, o));
    if ((tid & 31) == 0) red[tid >> 5] = m;
    __syncthreads();
    if (tid < 32) {
        float t = (tid < 8) ? red[tid] : -3.402823466e38f;
        #pragma unroll
        for (int o = 4; o; o >>= 1) t = fmaxf(t, __shfl_xor_sync(0xFFFFFFFFu, t, o));
        if (tid == 0) red[0] = t;
    }
    __syncthreads();
    m = red[0];
    __syncthreads();

    float s = 0.f;
    #pragma unroll
    for (int i = 0; i < 4; i++) {
        v[i].x = expf(v[i].x - m);
        v[i].y = expf(v[i].y - m);
        v[i].z = expf(v[i].z - m);
        v[i].w = expf(v[i].w - m);
        s += (v[i].x + v[i].y) + (v[i].z + v[i].w);
    }
    #pragma unroll
    for (int o = 16; o; o >>= 1) s += __shfl_xor_sync(0xFFFFFFFFu, s, o);
    if ((tid & 31) == 0) red[tid >> 5] = s;
    __syncthreads();
    if (tid < 32) {
        float t = (tid < 8) ? red[tid] : 0.f;
        #pragma unroll
        for (int o = 4; o; o >>= 1) t += __shfl_xor_sync(0xFFFFFFFFu, t, o);
        if (tid == 0) red[0] = t;
    }
    __syncthreads();
    const float inv = 1.0f / red[0];

    #pragma unroll
    for (int i = 0; i < 4; i++) {
        float4 o4 = make_float4(v[i].x * inv, v[i].y * inv, v[i].z * inv, v[i].w * inv);
        *(float4*)(p + (size_t)(tid + i * 256) * 4) = o4;
    }
}

// ---------------------------------------------------------------------------
// GEMM2: logits[b,c,d] = sum_s attn[b,c,s] * x[b,s,d]
// block tile 128(c) x 128(d), K over S. B (x) loaded natural [k][n] + ldmatrix.trans
// ---------------------------------------------------------------------------
__global__ __launch_bounds__(256) void gemm_logits_tc(
    const float* __restrict__ x, const float* __restrict__ attn,
    float* __restrict__ logits)
{
    __shared__ __align__(16) __nv_bfloat16 sAh[128 * PADA];
    __shared__ __align__(16) __nv_bfloat16 sAl[128 * PADA];
    __shared__ __align__(16) __nv_bfloat16 sBh[16 * PADB2];
    __shared__ __align__(16) __nv_bfloat16 sBl[16 * PADB2];

    const int b  = blockIdx.z;
    const int m0 = blockIdx.y * 128;   // c
    const int n0 = blockIdx.x * 128;   // d
    const float* Ab = attn + (size_t)b * C_ * S_;
    const float* xb = x + (size_t)b * S_ * D_;

    const int tid  = threadIdx.x;
    const int lane = tid & 31;
    const int wid  = tid >> 5;
    const int wm   = (wid >> 2) * 64;
    const int wn   = (wid & 3) * 32;

    const int a_r = lane & 15;
    const int a_c = (lane >> 4) * 8;
    uint32_t aAh = (uint32_t)__cvta_generic_to_shared(sAh);
    uint32_t aAl = (uint32_t)__cvta_generic_to_shared(sAl);
    uint32_t aBh = (uint32_t)__cvta_generic_to_shared(sBh);
    uint32_t aBl = (uint32_t)__cvta_generic_to_shared(sBl);
    uint32_t a_off[4], b_off[2];
    #pragma unroll
    for (int i = 0; i < 4; i++)
        a_off[i] = (uint32_t)(((wm + 16 * i + a_r) * PADA + a_c) * 2);
    #pragma unroll
    for (int j = 0; j < 2; j++) {
        int krow = ((lane >> 3) & 1) * 8 + (lane & 7);
        int ncol = wn + (2 * j + (lane >> 4)) * 8;
        b_off[j] = (uint32_t)((krow * PADB2 + ncol) * 2);
    }

    float acc[4][4][4];
    #pragma unroll
    for (int i = 0; i < 4; i++)
        #pragma unroll
        for (int j = 0; j < 4; j++)
            #pragma unroll
            for (int k = 0; k < 4; k++) acc[i][j][k] = 0.f;

    for (int kc = 0; kc < S_; kc += 16) {
        __syncthreads();
        // A: attn rows m0..+127, cols kc..kc+15
        #pragma unroll
        for (int i = 0; i < 2; i++) {
            int f = tid + i * 256;
            int row = f >> 2, cg = (f & 3) * 4;
            int c = m0 + row;
            float4 v = make_float4(0.f, 0.f, 0.f, 0.f);
            if (c < C_) v = *(const float4*)(Ab + (size_t)c * S_ + kc + cg);
            split_store4(v, &sAh[row * PADA + cg], &sAl[row * PADA + cg]);
        }
        // B: x rows kc..kc+15, cols n0..n0+127 (natural [k][n])
        #pragma unroll
        for (int i = 0; i < 2; i++) {
            int f = tid + i * 256;
            int krow = f >> 5, ncol = (f & 31) * 4;
            float4 v = *(const float4*)(xb + (size_t)(kc + krow) * D_ + n0 + ncol);
            split_store4(v, &sBh[krow * PADB2 + ncol], &sBl[krow * PADB2 + ncol]);
        }
        __syncthreads();

        uint32_t Ah[4][4], Al[4][4], Bh[2][4], Bl[2][4];
        #pragma unroll
        for (int i = 0; i < 4; i++) {
            ldsm_x4(Ah[i][0], Ah[i][1], Ah[i][2], Ah[i][3], aAh + a_off[i]);
            ldsm_x4(Al[i][0], Al[i][1], Al[i][2], Al[i][3], aAl + a_off[i]);
        }
        #pragma unroll
        for (int j = 0; j < 2; j++) {
            ldsm_x4_t(Bh[j][0], Bh[j][1], Bh[j][2], Bh[j][3], aBh + b_off[j]);
            ldsm_x4_t(Bl[j][0], Bl[j][1], Bl[j][2], Bl[j][3], aBl + b_off[j]);
        }

        #pragma unroll
        for (int mi = 0; mi < 4; mi++)
            #pragma unroll
            for (int nj = 0; nj < 4; nj++) {
                int jp = nj >> 1, s2 = (nj & 1) * 2;
                mma_bf16(acc[mi][nj], Ah[mi], Bh[jp][s2], Bh[jp][s2 + 1]);
                mma_bf16(acc[mi][nj], Ah[mi], Bl[jp][s2], Bl[jp][s2 + 1]);
                mma_bf16(acc[mi][nj], Al[mi], Bh[jp][s2], Bh[jp][s2 + 1]);
            }
    }

    float* outb = logits + (size_t)b * C_ * D_;
    #pragma unroll
    for (int mi = 0; mi < 4; mi++) {
        int c0r = m0 + wm + 16 * mi + (lane >> 2);
        #pragma unroll
        for (int nj = 0; nj < 4; nj++) {
            int d = n0 + wn + 8 * nj + (lane & 3) * 2;
            if (c0r < C_)
                *(float2*)(outb + (size_t)c0r * D_ + d) = make_float2(acc[mi][nj][0], acc[mi][nj][1]);
            if (c0r + 8 < C_)
                *(float2*)(outb + (size_t)(c0r + 8) * D_ + d) = make_float2(acc[mi][nj][2], acc[mi][nj][3]);
        }
    }
}

// ---------------------------------------------------------------------------
extern "C" void kernel_launch(void* const* d_in, const int* in_sizes, int n_in,
                              void* d_out, int out_size)
{
    const float* x = (const float*)d_in[0];   // [B, S, D]
    const float* W = (const float*)d_in[1];   // [C, D]

    float* logits = (float*)d_out;                            // [B, C, D]
    float* attn   = (float*)d_out + (size_t)B_ * C_ * D_;     // [B, C, S]

    dim3 g1(S_ / 128, (C_ + 127) / 128, B_);
    gemm_scores_tc<<<g1, 256>>>(x, W, attn);

    softmax_rows_kernel<<<B_ * C_, 256>>>(attn);

    dim3 g3(D_ / 128, (C_ + 127) / 128, B_);
    gemm_logits_tc<<<g3, 256>>>(x, attn, logits);
}

// round 8
// speedup vs baseline: 2.3999x; 1.0018x over previous
#include <cuda_runtime.h>
#include <cuda_bf16.h>
#include <cstdint>

// LabelwiseAttention: B=4, S=4096, D=256, C=8921
//   scores[b,c,s] = sum_d x[b,s,d] * W[c,d]
//   attn          = softmax_s(scores)
//   logits[b,c,d] = sum_s attn[b,c,s] * x[b,s,d]
// d_out = [logits (B*C*D) | attention (B*C*S)], fp32.
//
// Legacy mma.sync bf16 hi/lo split (3 terms), cp.async double-buffered,
// 128x256 block tiles, 64x64 warp tiles. Inputs pre-split to bf16 scratch;
// softmax emits attn bf16 splits so GEMM2 loads are pure copies.

#define B_ 4
#define S_ 4096
#define D_ 256
#define C_ 8921
#define CPAD 9088
#define CTILES 70   // ceil(C/128)

// ---- bf16 hi/lo scratch (zero-initialized; pad rows stay zero) -------------
__device__ __nv_bfloat16 g_wh[(size_t)CPAD * D_];
__device__ __nv_bfloat16 g_wl[(size_t)CPAD * D_];
__device__ __nv_bfloat16 g_xh[(size_t)B_ * S_ * D_];
__device__ __nv_bfloat16 g_xl[(size_t)B_ * S_ * D_];
__device__ __nv_bfloat16 g_ah[(size_t)B_ * CPAD * S_];
__device__ __nv_bfloat16 g_al[(size_t)B_ * CPAD * S_];

// ---- helpers ---------------------------------------------------------------
__device__ __forceinline__ uint32_t smem_u32(const void* p) {
    uint32_t a;
    asm("{ .reg .u64 t; cvta.to.shared.u64 t, %1; cvt.u32.u64 %0, t; }" : "=r"(a) : "l"(p));
    return a;
}
__device__ __forceinline__ void cp16(uint32_t dst, const void* src) {
    size_t g;
    asm("cvta.to.global.u64 %0, %1;" : "=l"(g) : "l"(src));
    asm volatile("cp.async.cg.shared.global [%0], [%1], 16;\n" :: "r"(dst), "l"(g));
}
__device__ __forceinline__ void cp_commit() {
    asm volatile("cp.async.commit_group;\n" ::: "memory");
}
__device__ __forceinline__ void cp_wait0() {
    asm volatile("cp.async.wait_group 0;\n" ::: "memory");
}
__device__ __forceinline__ void cp_wait1() {
    asm volatile("cp.async.wait_group 1;\n" ::: "memory");
}
__device__ __forceinline__ void ldsm_x4(uint32_t* r, uint32_t addr) {
    asm volatile("ldmatrix.sync.aligned.m8n8.x4.shared.b16 {%0,%1,%2,%3}, [%4];\n"
                 : "=r"(r[0]), "=r"(r[1]), "=r"(r[2]), "=r"(r[3]) : "r"(addr));
}
__device__ __forceinline__ void ldsm_x4_t(uint32_t* r, uint32_t addr) {
    asm volatile("ldmatrix.sync.aligned.m8n8.x4.trans.shared.b16 {%0,%1,%2,%3}, [%4];\n"
                 : "=r"(r[0]), "=r"(r[1]), "=r"(r[2]), "=r"(r[3]) : "r"(addr));
}
__device__ __forceinline__ void mma_bf16(float* c, const uint32_t* a, uint32_t b0, uint32_t b1) {
    asm volatile(
        "mma.sync.aligned.m16n8k16.row.col.f32.bf16.bf16.f32 "
        "{%0,%1,%2,%3}, {%4,%5,%6,%7}, {%8,%9}, {%0,%1,%2,%3};\n"
        : "+f"(c[0]), "+f"(c[1]), "+f"(c[2]), "+f"(c[3])
        : "r"(a[0]), "r"(a[1]), "r"(a[2]), "r"(a[3]), "r"(b0), "r"(b1));
}
__device__ __forceinline__ void split2(float a, float b, uint32_t& h, uint32_t& l) {
    __nv_bfloat16 ha = __float2bfloat16_rn(a), hb = __float2bfloat16_rn(b);
    __nv_bfloat16 la = __float2bfloat16_rn(a - __bfloat162float(ha));
    __nv_bfloat16 lb = __float2bfloat16_rn(b - __bfloat162float(hb));
    __nv_bfloat162 hh = __halves2bfloat162(ha, hb), ll = __halves2bfloat162(la, lb);
    h = *reinterpret_cast<uint32_t*>(&hh);
    l = *reinterpret_cast<uint32_t*>(&ll);
}

// ---- input split kernels ---------------------------------------------------
__global__ __launch_bounds__(256) void split_kernel(
    const float* __restrict__ src, __nv_bfloat16* __restrict__ dh,
    __nv_bfloat16* __restrict__ dl, int n4)
{
    int i = blockIdx.x * 256 + threadIdx.x;
    if (i >= n4) return;
    float4 v = ((const float4*)src)[i];
    uint32_t h0, l0, h1, l1;
    split2(v.x, v.y, h0, l0);
    split2(v.z, v.w, h1, l1);
    ((uint2*)dh)[i] = make_uint2(h0, h1);
    ((uint2*)dl)[i] = make_uint2(l0, l1);
}

// ---- GEMM1: scores = W . x^T; block 128(c) x 256(s), K=D=256, k-chunk 32 ----
// smem stage layout (bytes): Ah[128][40]b16 @0 (10240), Al @10240,
//                            Bh[256][40]   @20480 (20480), Bl @40960
#define G1_STAGE 61440
__global__ __launch_bounds__(256, 1) void gemm1_k(float* __restrict__ scores)
{
    extern __shared__ char smem[];
    const uint32_t sb = smem_u32(smem);
    const int tid = threadIdx.x, lane = tid & 31, wid = tid >> 5;
    const int b = blockIdx.z, m0 = blockIdx.y * 128, n0 = blockIdx.x * 256;
    const int wm = (wid >> 2) * 64, wn = (wid & 3) * 64;
    const size_t xoff = (size_t)b * S_ * D_;

    float acc[4][8][4];
    #pragma unroll
    for (int i = 0; i < 4; i++)
        #pragma unroll
        for (int j = 0; j < 8; j++)
            #pragma unroll
            for (int k = 0; k < 4; k++) acc[i][j][k] = 0.f;

    // ldmatrix lane-invariant offset components
    const uint32_t a_row = (uint32_t)(lane & 15), a_col = (uint32_t)((lane >> 4) * 8);
    const uint32_t b_sub = (uint32_t)(((lane >> 3) & 1) * 8);
    const uint32_t b_lo  = (uint32_t)(lane & 7), b_hi = (uint32_t)(lane >> 4);

    auto load_stage = [&](int kc, uint32_t stg) {
        #pragma unroll
        for (int i = 0; i < 4; i++) {
            int u = tid + i * 256;
            int row = u >> 3, half = (u >> 2) & 1, ch = u & 3;
            const __nv_bfloat16* src =
                (half ? g_wl : g_wh) + (size_t)(m0 + row) * D_ + kc + ch * 8;
            cp16(sb + stg + (uint32_t)(half * 10240 + row * 80 + ch * 16), src);
        }
        #pragma unroll
        for (int i = 0; i < 8; i++) {
            int u = tid + i * 256;
            int row = u >> 3, half = (u >> 2) & 1, ch = u & 3;
            const __nv_bfloat16* src =
                (half ? g_xl : g_xh) + xoff + (size_t)(n0 + row) * D_ + kc + ch * 8;
            cp16(sb + stg + (uint32_t)(20480 + half * 20480 + row * 80 + ch * 16), src);
        }
        cp_commit();
    };

    load_stage(0, 0);
    #pragma unroll 1
    for (int c = 0; c < 8; c++) {
        if (c < 7) { load_stage((c + 1) * 32, (uint32_t)(((c + 1) & 1) * G1_STAGE)); cp_wait1(); }
        else cp_wait0();
        __syncthreads();
        const uint32_t stg = sb + (uint32_t)((c & 1) * G1_STAGE);
        #pragma unroll
        for (int ks = 0; ks < 2; ks++) {
            uint32_t Ah[4][4], Al[4][4], Bh[4][4], Bl[4][4];
            #pragma unroll
            for (int mi = 0; mi < 4; mi++) {
                uint32_t a = stg + (uint32_t)(wm + 16 * mi + a_row) * 80 + (a_col + ks * 16) * 2;
                ldsm_x4(Ah[mi], a);
                ldsm_x4(Al[mi], a + 10240);
            }
            #pragma unroll
            for (int jj = 0; jj < 4; jj++) {
                uint32_t nrow = (uint32_t)(wn + (2 * jj + b_hi) * 8 + b_lo);
                uint32_t a = stg + 20480 + nrow * 80 + (b_sub + ks * 16) * 2;
                ldsm_x4(Bh[jj], a);
                ldsm_x4(Bl[jj], a + 20480);
            }
            #pragma unroll
            for (int mi = 0; mi < 4; mi++)
                #pragma unroll
                for (int nj = 0; nj < 8; nj++) {
                    int jp = nj >> 1, s2 = (nj & 1) * 2;
                    mma_bf16(acc[mi][nj], Ah[mi], Bh[jp][s2], Bh[jp][s2 + 1]);
                    mma_bf16(acc[mi][nj], Ah[mi], Bl[jp][s2], Bl[jp][s2 + 1]);
                    mma_bf16(acc[mi][nj], Al[mi], Bh[jp][s2], Bh[jp][s2 + 1]);
                }
        }
        __syncthreads();
    }

    // epilogue: fp32 scores into d_out attention region
    float* outb = scores + (size_t)b * C_ * S_;
    #pragma unroll
    for (int mi = 0; mi < 4; mi++) {
        int c0 = m0 + wm + 16 * mi + (lane >> 2);
        #pragma unroll
        for (int nj = 0; nj < 8; nj++) {
            int s = n0 + wn + 8 * nj + (lane & 3) * 2;
            if (c0 < C_)
                *(float2*)(outb + (size_t)c0 * S_ + s) = make_float2(acc[mi][nj][0], acc[mi][nj][1]);
            if (c0 + 8 < C_)
                *(float2*)(outb + (size_t)(c0 + 8) * S_ + s) = make_float2(acc[mi][nj][2], acc[mi][nj][3]);
        }
    }
}

// ---- softmax: in-place fp32 + bf16 hi/lo split outputs ---------------------
__global__ __launch_bounds__(256) void softmax_k(float* __restrict__ attn)
{
    const int bx = blockIdx.x;            // b*C_ + c
    const int b = bx / C_, c = bx % C_;
    float* p = attn + (size_t)bx * S_;
    __nv_bfloat16* ah = g_ah + ((size_t)b * CPAD + c) * S_;
    __nv_bfloat16* al = g_al + ((size_t)b * CPAD + c) * S_;
    const int tid = threadIdx.x;

    float4 v[4];
    float m = -3.402823466e38f;
    #pragma unroll
    for (int i = 0; i < 2; i++) {
        int e0 = (tid + i * 256) * 8;
        v[2 * i]     = *(const float4*)(p + e0);
        v[2 * i + 1] = *(const float4*)(p + e0 + 4);
    }
    #pragma unroll
    for (int i = 0; i < 4; i++)
        m = fmaxf(m, fmaxf(fmaxf(v[i].x, v[i].y), fmaxf(v[i].z, v[i].w)));

    __shared__ float red[8];
    #pragma unroll
    for (int o = 16; o; o >>= 1) m = fmaxf(m, __shfl_xor_sync(0xFFFFFFFFu, m, o));
    if ((tid & 31) == 0) red[tid >> 5] = m;
    __syncthreads();
    if (tid < 32) {
        float t = (tid < 8) ? red[tid] : -3.402823466e38f;
        #pragma unroll
        for (int o = 4; o; o >>= 1) t = fmaxf(t, __shfl_xor_sync(0xFFFFFFFFu, t, o));
        if (tid == 0) red[0] = t;
    }
    __syncthreads();
    m = red[0];
    __syncthreads();

    float s = 0.f;
    #pragma unroll
    for (int i = 0; i < 4; i++) {
        v[i].x = __expf(v[i].x - m);
        v[i].y = __expf(v[i].y - m);
        v[i].z = __expf(v[i].z - m);
        v[i].w = __expf(v[i].w - m);
        s += (v[i].x + v[i].y) + (v[i].z + v[i].w);
    }
    #pragma unroll
    for (int o = 16; o; o >>= 1) s += __shfl_xor_sync(0xFFFFFFFFu, s, o);
    if ((tid & 31) == 0) red[tid >> 5] = s;
    __syncthreads();
    if (tid < 32) {
        float t = (tid < 8) ? red[tid] : 0.f;
        #pragma unroll
        for (int o = 4; o; o >>= 1) t += __shfl_xor_sync(0xFFFFFFFFu, t, o);
        if (tid == 0) red[0] = t;
    }
    __syncthreads();
    const float inv = 1.0f / red[0];

    #pragma unroll
    for (int i = 0; i < 2; i++) {
        int e0 = (tid + i * 256) * 8;
        float4 a4 = v[2 * i], b4 = v[2 * i + 1];
        a4.x *= inv; a4.y *= inv; a4.z *= inv; a4.w *= inv;
        b4.x *= inv; b4.y *= inv; b4.z *= inv; b4.w *= inv;
        *(float4*)(p + e0)     = a4;
        *(float4*)(p + e0 + 4) = b4;
        uint4 hh, ll;
        split2(a4.x, a4.y, hh.x, ll.x);
        split2(a4.z, a4.w, hh.y, ll.y);
        split2(b4.x, b4.y, hh.z, ll.z);
        split2(b4.z, b4.w, hh.w, ll.w);
        *(uint4*)(ah + e0) = hh;
        *(uint4*)(al + e0) = ll;
    }
}

// ---- GEMM2: logits = attn . x; block 128(c) x 256(d=all), K=S, k-chunk 32 --
// smem stage: Ah[128][40] @0, Al @10240, Bh[32][264] @20480 (16896), Bl @37376
#define G2_STAGE 54272
__global__ __launch_bounds__(256, 1) void gemm2_k(float* __restrict__ logits)
{
    extern __shared__ char smem[];
    const uint32_t sb = smem_u32(smem);
    const int tid = threadIdx.x, lane = tid & 31, wid = tid >> 5;
    const int b = blockIdx.z, m0 = blockIdx.y * 128;
    const int wm = (wid >> 2) * 64, wn = (wid & 3) * 64;
    const size_t xoff = (size_t)b * S_ * D_;
    const size_t aoff = (size_t)b * CPAD * S_;

    float acc[4][8][4];
    #pragma unroll
    for (int i = 0; i < 4; i++)
        #pragma unroll
        for (int j = 0; j < 8; j++)
            #pragma unroll
            for (int k = 0; k < 4; k++) acc[i][j][k] = 0.f;

    const uint32_t a_row = (uint32_t)(lane & 15), a_col = (uint32_t)((lane >> 4) * 8);
    const uint32_t b_k8  = (uint32_t)(((lane >> 3) & 1) * 8 + (lane & 7));
    const uint32_t b_hi  = (uint32_t)(lane >> 4);

    auto load_stage = [&](int kc, uint32_t stg) {
        #pragma unroll
        for (int i = 0; i < 4; i++) {
            int u = tid + i * 256;
            int row = u >> 3, half = (u >> 2) & 1, ch = u & 3;
            const __nv_bfloat16* src =
                (half ? g_al : g_ah) + aoff + (size_t)(m0 + row) * S_ + kc + ch * 8;
            cp16(sb + stg + (uint32_t)(half * 10240 + row * 80 + ch * 16), src);
        }
        #pragma unroll
        for (int i = 0; i < 8; i++) {
            int u = tid + i * 256;
            int row = u >> 6, half = (u >> 5) & 1, ch = u & 31;
            const __nv_bfloat16* src =
                (half ? g_xl : g_xh) + xoff + (size_t)(kc + row) * D_ + ch * 8;
            cp16(sb + stg + (uint32_t)(20480 + half * 16896 + row * 528 + ch * 16), src);
        }
        cp_commit();
    };

    load_stage(0, 0);
    #pragma unroll 1
    for (int c = 0; c < 128; c++) {
        if (c < 127) { load_stage((c + 1) * 32, (uint32_t)(((c + 1) & 1) * G2_STAGE)); cp_wait1(); }
        else cp_wait0();
        __syncthreads();
        const uint32_t stg = sb + (uint32_t)((c & 1) * G2_STAGE);
        #pragma unroll
        for (int ks = 0; ks < 2; ks++) {
            uint32_t Ah[4][4], Al[4][4], Bh[4][4], Bl[4][4];
            #pragma unroll
            for (int mi = 0; mi < 4; mi++) {
                uint32_t a = stg + (uint32_t)(wm + 16 * mi + a_row) * 80 + (a_col + ks * 16) * 2;
                ldsm_x4(Ah[mi], a);
                ldsm_x4(Al[mi], a + 10240);
            }
            #pragma unroll
            for (int jj = 0; jj < 4; jj++) {
                uint32_t krow = (uint32_t)(ks * 16) + b_k8;
                uint32_t ncol = (uint32_t)(wn + (2 * jj + b_hi) * 8);
                uint32_t a = stg + 20480 + krow * 528 + ncol * 2;
                ldsm_x4_t(Bh[jj], a);
                ldsm_x4_t(Bl[jj], a + 16896);
            }
            #pragma unroll
            for (int mi = 0; mi < 4; mi++)
                #pragma unroll
                for (int nj = 0; nj < 8; nj++) {
                    int jp = nj >> 1, s2 = (nj & 1) * 2;
                    mma_bf16(acc[mi][nj], Ah[mi], Bh[jp][s2], Bh[jp][s2 + 1]);
                    mma_bf16(acc[mi][nj], Ah[mi], Bl[jp][s2], Bl[jp][s2 + 1]);
                    mma_bf16(acc[mi][nj], Al[mi], Bh[jp][s2], Bh[jp][s2 + 1]);
                }
        }
        __syncthreads();
    }

    float* outb = logits + (size_t)b * C_ * D_;
    #pragma unroll
    for (int mi = 0; mi < 4; mi++) {
        int c0 = m0 + wm + 16 * mi + (lane >> 2);
        #pragma unroll
        for (int nj = 0; nj < 8; nj++) {
            int d = wn + 8 * nj + (lane & 3) * 2;
            if (c0 < C_)
                *(float2*)(outb + (size_t)c0 * D_ + d) = make_float2(acc[mi][nj][0], acc[mi][nj][1]);
            if (c0 + 8 < C_)
                *(float2*)(outb + (size_t)(c0 + 8) * D_ + d) = make_float2(acc[mi][nj][2], acc[mi][nj][3]);
        }
    }
}

// ---------------------------------------------------------------------------
extern "C" void kernel_launch(void* const* d_in, const int* in_sizes, int n_in,
                              void* d_out, int out_size)
{
    const float* x = (const float*)d_in[0];   // [B, S, D]
    const float* W = (const float*)d_in[1];   // [C, D]

    float* logits = (float*)d_out;                            // [B, C, D]
    float* attn   = (float*)d_out + (size_t)B_ * C_ * D_;     // [B, C, S]

    cudaFuncSetAttribute(gemm1_k, cudaFuncAttributeMaxDynamicSharedMemorySize, 2 * G1_STAGE);
    cudaFuncSetAttribute(gemm2_k, cudaFuncAttributeMaxDynamicSharedMemorySize, 2 * G2_STAGE);

    __nv_bfloat16 *p_wh, *p_wl, *p_xh, *p_xl;
    cudaGetSymbolAddress((void**)&p_wh, g_wh);
    cudaGetSymbolAddress((void**)&p_wl, g_wl);
    cudaGetSymbolAddress((void**)&p_xh, g_xh);
    cudaGetSymbolAddress((void**)&p_xl, g_xl);

    const int nw4 = C_ * D_ / 4;
    const int nx4 = B_ * S_ * D_ / 4;
    split_kernel<<<(nw4 + 255) / 256, 256>>>(W, p_wh, p_wl, nw4);
    split_kernel<<<(nx4 + 255) / 256, 256>>>(x, p_xh, p_xl, nx4);

    gemm1_k<<<dim3(S_ / 256, CTILES, B_), 256, 2 * G1_STAGE>>>(attn);

    softmax_k<<<B_ * C_, 256>>>(attn);

    gemm2_k<<<dim3(1, CTILES, B_), 256, 2 * G2_STAGE>>>(logits);
}

// round 10
// speedup vs baseline: 2.8307x; 1.1795x over previous
#include <cuda_runtime.h>
#include <cuda_bf16.h>
#include <cstdint>

// LabelwiseAttention: B=4, S=4096, D=256, C=8921
//   scores[b,c,s] = sum_d x[b,s,d] * W[c,d]
//   attn          = softmax_s(scores)
//   logits[b,c,d] = sum_s attn[b,c,s] * x[b,s,d]
// d_out = [logits (B*C*D) | attention (B*C*S)], fp32.
//
// bf16 hi/lo split mma.sync (3 terms), cp.async double-buffered.
// Softmax is FUSED: gemm1 epilogue emits per-(row, s-block) (max, sumexp)
// partials; rstats combines them; gemm2's A-loader applies exp/normalize to
// the raw scores (in d_out), writes normalized attention back in place, and
// feeds bf16 hi/lo fragments to the tensor cores.

#define B_ 4
#define S_ 4096
#define D_ 256
#define C_ 8921
#define CPAD 9088
#define CTILES 70        // ceil(C/128)
#define NSB 32           // s-blocks in gemm1 (S/128)

// ---- scratch ---------------------------------------------------------------
__device__ __nv_bfloat16 g_wh[(size_t)CPAD * D_];
__device__ __nv_bfloat16 g_wl[(size_t)CPAD * D_];
__device__ __nv_bfloat16 g_xh[(size_t)B_ * S_ * D_];
__device__ __nv_bfloat16 g_xl[(size_t)B_ * S_ * D_];
__device__ float2 g_part[(size_t)B_ * CPAD * NSB];   // per (row, s-block) (m, l)
__device__ float2 g_stats[(size_t)B_ * CPAD];        // per row (M, 1/L)

// ---- helpers ---------------------------------------------------------------
__device__ __forceinline__ uint32_t smem_u32(const void* p) {
    uint32_t a;
    asm("{ .reg .u64 t; cvta.to.shared.u64 t, %1; cvt.u32.u64 %0, t; }" : "=r"(a) : "l"(p));
    return a;
}
__device__ __forceinline__ void cp16(uint32_t dst, const void* src) {
    size_t g;
    asm("cvta.to.global.u64 %0, %1;" : "=l"(g) : "l"(src));
    asm volatile("cp.async.cg.shared.global [%0], [%1], 16;\n" :: "r"(dst), "l"(g));
}
__device__ __forceinline__ void cp_commit() { asm volatile("cp.async.commit_group;\n" ::: "memory"); }
__device__ __forceinline__ void cp_wait0()  { asm volatile("cp.async.wait_group 0;\n" ::: "memory"); }
__device__ __forceinline__ void cp_wait1()  { asm volatile("cp.async.wait_group 1;\n" ::: "memory"); }
__device__ __forceinline__ void ldsm_x4(uint32_t* r, uint32_t addr) {
    asm volatile("ldmatrix.sync.aligned.m8n8.x4.shared.b16 {%0,%1,%2,%3}, [%4];\n"
                 : "=r"(r[0]), "=r"(r[1]), "=r"(r[2]), "=r"(r[3]) : "r"(addr));
}
__device__ __forceinline__ void ldsm_x4_t(uint32_t* r, uint32_t addr) {
    asm volatile("ldmatrix.sync.aligned.m8n8.x4.trans.shared.b16 {%0,%1,%2,%3}, [%4];\n"
                 : "=r"(r[0]), "=r"(r[1]), "=r"(r[2]), "=r"(r[3]) : "r"(addr));
}
__device__ __forceinline__ void mma_bf16(float* c, const uint32_t* a, uint32_t b0, uint32_t b1) {
    asm volatile(
        "mma.sync.aligned.m16n8k16.row.col.f32.bf16.bf16.f32 "
        "{%0,%1,%2,%3}, {%4,%5,%6,%7}, {%8,%9}, {%0,%1,%2,%3};\n"
        : "+f"(c[0]), "+f"(c[1]), "+f"(c[2]), "+f"(c[3])
        : "r"(a[0]), "r"(a[1]), "r"(a[2]), "r"(a[3]), "r"(b0), "r"(b1));
}
__device__ __forceinline__ void split2(float a, float b, uint32_t& h, uint32_t& l) {
    __nv_bfloat16 ha = __float2bfloat16_rn(a), hb = __float2bfloat16_rn(b);
    __nv_bfloat16 la = __float2bfloat16_rn(a - __bfloat162float(ha));
    __nv_bfloat16 lb = __float2bfloat16_rn(b - __bfloat162float(hb));
    __nv_bfloat162 hh = __halves2bfloat162(ha, hb), ll = __halves2bfloat162(la, lb);
    h = *reinterpret_cast<uint32_t*>(&hh);
    l = *reinterpret_cast<uint32_t*>(&ll);
}

// ---- input split -----------------------------------------------------------
__global__ __launch_bounds__(256) void split_kernel(
    const float* __restrict__ src, __nv_bfloat16* __restrict__ dh,
    __nv_bfloat16* __restrict__ dl, int n4)
{
    int i = blockIdx.x * 256 + threadIdx.x;
    if (i >= n4) return;
    float4 v = ((const float4*)src)[i];
    uint32_t h0, l0, h1, l1;
    split2(v.x, v.y, h0, l0);
    split2(v.z, v.w, h1, l1);
    ((uint2*)dh)[i] = make_uint2(h0, h1);
    ((uint2*)dl)[i] = make_uint2(l0, l1);
}

// ---- GEMM1: scores = W . x^T; block 128(c) x 128(s), k-chunk 32 ------------
// stage (bytes): Ah[128 rows x 80B] @0 (10240), Al @10240, Bh @20480, Bl @30720
#define G1_STAGE 40960
__global__ __launch_bounds__(256, 2) void gemm1_k(float* __restrict__ scores)
{
    extern __shared__ char smem[];
    const uint32_t sb = smem_u32(smem);
    const int tid = threadIdx.x, lane = tid & 31, wid = tid >> 5;
    const int b = blockIdx.z, m0 = blockIdx.y * 128, n0 = blockIdx.x * 128;
    const int wm = (wid >> 2) * 64, wn = (wid & 3) * 32;
    const size_t xoff = (size_t)b * S_ * D_;

    float acc[4][4][4];
    #pragma unroll
    for (int i = 0; i < 4; i++)
        #pragma unroll
        for (int j = 0; j < 4; j++)
            #pragma unroll
            for (int k = 0; k < 4; k++) acc[i][j][k] = 0.f;

    const uint32_t a_row = (uint32_t)(lane & 15), a_col = (uint32_t)((lane >> 4) * 8);
    const uint32_t b_sub = (uint32_t)(((lane >> 3) & 1) * 8);
    const uint32_t b_lo  = (uint32_t)(lane & 7), b_hi = (uint32_t)(lane >> 4);

    auto load_stage = [&](int kc, uint32_t stg) {
        #pragma unroll
        for (int i = 0; i < 4; i++) {   // A: 128 rows x 32 b16 x 2 halves
            int u = tid + i * 256;
            int row = u >> 3, half = (u >> 2) & 1, ch = u & 3;
            const __nv_bfloat16* src =
                (half ? g_wl : g_wh) + (size_t)(m0 + row) * D_ + kc + ch * 8;
            cp16(sb + stg + (uint32_t)(half * 10240 + row * 80 + ch * 16), src);
        }
        #pragma unroll
        for (int i = 0; i < 4; i++) {   // B: 128 rows (s) x 32 b16 x 2 halves
            int u = tid + i * 256;
            int row = u >> 3, half = (u >> 2) & 1, ch = u & 3;
            const __nv_bfloat16* src =
                (half ? g_xl : g_xh) + xoff + (size_t)(n0 + row) * D_ + kc + ch * 8;
            cp16(sb + stg + (uint32_t)(20480 + half * 10240 + row * 80 + ch * 16), src);
        }
        cp_commit();
    };

    load_stage(0, 0);
    #pragma unroll 1
    for (int c = 0; c < 8; c++) {
        if (c < 7) { load_stage((c + 1) * 32, (uint32_t)(((c + 1) & 1) * G1_STAGE)); cp_wait1(); }
        else cp_wait0();
        __syncthreads();
        const uint32_t stg = sb + (uint32_t)((c & 1) * G1_STAGE);
        #pragma unroll
        for (int ks = 0; ks < 2; ks++) {
            uint32_t Ah[4][4], Al[4][4], Bh[2][4], Bl[2][4];
            #pragma unroll
            for (int mi = 0; mi < 4; mi++) {
                uint32_t a = stg + (uint32_t)(wm + 16 * mi + a_row) * 80 + (a_col + ks * 16) * 2;
                ldsm_x4(Ah[mi], a);
                ldsm_x4(Al[mi], a + 10240);
            }
            #pragma unroll
            for (int jj = 0; jj < 2; jj++) {
                uint32_t nrow = (uint32_t)(wn + (2 * jj + b_hi) * 8 + b_lo);
                uint32_t a = stg + 20480 + nrow * 80 + (b_sub + ks * 16) * 2;
                ldsm_x4(Bh[jj], a);
                ldsm_x4(Bl[jj], a + 10240);
            }
            #pragma unroll
            for (int mi = 0; mi < 4; mi++)
                #pragma unroll
                for (int nj = 0; nj < 4; nj++) {
                    int jp = nj >> 1, s2 = (nj & 1) * 2;
                    mma_bf16(acc[mi][nj], Ah[mi], Bh[jp][s2], Bh[jp][s2 + 1]);
                    mma_bf16(acc[mi][nj], Ah[mi], Bl[jp][s2], Bl[jp][s2 + 1]);
                    mma_bf16(acc[mi][nj], Al[mi], Bh[jp][s2], Bh[jp][s2 + 1]);
                }
        }
        __syncthreads();
    }

    // raw scores -> d_out attention region
    float* outb = scores + (size_t)b * C_ * S_;
    #pragma unroll
    for (int mi = 0; mi < 4; mi++) {
        int c0 = m0 + wm + 16 * mi + (lane >> 2);
        #pragma unroll
        for (int nj = 0; nj < 4; nj++) {
            int s = n0 + wn + 8 * nj + (lane & 3) * 2;
            if (c0 < C_)
                *(float2*)(outb + (size_t)c0 * S_ + s) = make_float2(acc[mi][nj][0], acc[mi][nj][1]);
            if (c0 + 8 < C_)
                *(float2*)(outb + (size_t)(c0 + 8) * S_ + s) = make_float2(acc[mi][nj][2], acc[mi][nj][3]);
        }
    }

    // --- per-row softmax partials over this 128-col s-block ---
    __syncthreads();                       // safe to reuse stage smem
    float* sm_m = (float*)smem;            // [128][4]
    float* sm_f = (float*)smem + 512;      // [128]
    float* sm_l = (float*)smem + 640;      // [128][4]

    #pragma unroll
    for (int mi = 0; mi < 4; mi++)
        #pragma unroll
        for (int h = 0; h < 2; h++) {
            int r = wm + 16 * mi + (lane >> 2) + 8 * h;
            float vm = -3.402823466e38f;
            #pragma unroll
            for (int nj = 0; nj < 4; nj++)
                vm = fmaxf(vm, fmaxf(acc[mi][nj][2 * h], acc[mi][nj][2 * h + 1]));
            vm = fmaxf(vm, __shfl_xor_sync(0xFFFFFFFFu, vm, 1));
            vm = fmaxf(vm, __shfl_xor_sync(0xFFFFFFFFu, vm, 2));
            if ((lane & 3) == 0) sm_m[r * 4 + (wid & 3)] = vm;
        }
    __syncthreads();
    if (tid < 128) {
        float m = fmaxf(fmaxf(sm_m[tid * 4], sm_m[tid * 4 + 1]),
                        fmaxf(sm_m[tid * 4 + 2], sm_m[tid * 4 + 3]));
        sm_f[tid] = m;
    }
    __syncthreads();
    #pragma unroll
    for (int mi = 0; mi < 4; mi++)
        #pragma unroll
        for (int h = 0; h < 2; h++) {
            int r = wm + 16 * mi + (lane >> 2) + 8 * h;
            float m = sm_f[r], ls = 0.f;
            #pragma unroll
            for (int nj = 0; nj < 4; nj++)
                ls += __expf(acc[mi][nj][2 * h] - m) + __expf(acc[mi][nj][2 * h + 1] - m);
            ls += __shfl_xor_sync(0xFFFFFFFFu, ls, 1);
            ls += __shfl_xor_sync(0xFFFFFFFFu, ls, 2);
            if ((lane & 3) == 0) sm_l[r * 4 + (wid & 3)] = ls;
        }
    __syncthreads();
    if (tid < 128) {
        int c = m0 + tid;
        if (c < C_) {
            float l = sm_l[tid * 4] + sm_l[tid * 4 + 1] + sm_l[tid * 4 + 2] + sm_l[tid * 4 + 3];
            g_part[((size_t)b * CPAD + c) * NSB + blockIdx.x] = make_float2(sm_f[tid], l);
        }
    }
}

// ---- rstats: combine NSB partials per row -> (M, 1/L) ----------------------
__global__ __launch_bounds__(256) void rstats_k()
{
    int idx = blockIdx.x * 256 + threadIdx.x;
    if (idx >= B_ * C_) return;
    int b = idx / C_, c = idx % C_;
    const float2* p = &g_part[((size_t)b * CPAD + c) * NSB];
    float M = -3.402823466e38f;
    #pragma unroll
    for (int i = 0; i < NSB; i++) M = fmaxf(M, p[i].x);
    float L = 0.f;
    #pragma unroll
    for (int i = 0; i < NSB; i++) L += p[i].y * __expf(p[i].x - M);
    g_stats[(size_t)b * CPAD + c] = make_float2(M, 1.0f / L);
}

// ---- GEMM2: logits = attn . x; block 128(c) x 256(d), 512 thr, k-chunk 32 --
// stage: Ah[128x80B] @0 (10240), Al @10240, Bh[32x528B] @20480 (16896), Bl @37376
#define G2_STAGE 54272
__global__ __launch_bounds__(512, 1) void gemm2_k(float* __restrict__ attn,
                                                  float* __restrict__ logits)
{
    extern __shared__ char smem[];
    const uint32_t sb = smem_u32(smem);
    const int tid = threadIdx.x, lane = tid & 31, wid = tid >> 5;
    const int b = blockIdx.z, m0 = blockIdx.y * 128;
    const int wm = (wid >> 2) * 32, wn = (wid & 3) * 64;
    const size_t xoff = (size_t)b * S_ * D_;

    float acc[2][8][4];
    #pragma unroll
    for (int i = 0; i < 2; i++)
        #pragma unroll
        for (int j = 0; j < 8; j++)
            #pragma unroll
            for (int k = 0; k < 4; k++) acc[i][j][k] = 0.f;

    const uint32_t a_row = (uint32_t)(lane & 15), a_col = (uint32_t)((lane >> 4) * 8);
    const uint32_t b_k8  = (uint32_t)(((lane >> 3) & 1) * 8 + (lane & 7));
    const uint32_t b_hi  = (uint32_t)(lane >> 4);

    // A-loader mapping: each thread owns one score row, 8 fp32 per chunk
    const int arow = tid >> 2;               // 0..127
    const int acg  = (tid & 3) * 8;          // col group within chunk
    const int cglob = m0 + arow;
    const bool avalid = cglob < C_;
    float* aptr = attn + ((size_t)b * C_ + cglob) * S_ + acg;   // valid only if avalid
    float M = 0.f, invL = 0.f;
    if (avalid) {
        float2 st = g_stats[(size_t)b * CPAD + cglob];
        M = st.x; invL = st.y;
    }

    auto ldgA = [&](int kc, float4& f0, float4& f1) {
        if (avalid) {
            f0 = *(const float4*)(aptr + kc);
            f1 = *(const float4*)(aptr + kc + 4);
        }
    };
    auto procA = [&](int kc, uint32_t stg, float4 f0, float4 f1) {
        uint32_t dst = sb + stg + (uint32_t)(arow * 80 + acg * 2);
        if (avalid) {
            float4 p0, p1;
            p0.x = __expf(f0.x - M) * invL; p0.y = __expf(f0.y - M) * invL;
            p0.z = __expf(f0.z - M) * invL; p0.w = __expf(f0.w - M) * invL;
            p1.x = __expf(f1.x - M) * invL; p1.y = __expf(f1.y - M) * invL;
            p1.z = __expf(f1.z - M) * invL; p1.w = __expf(f1.w - M) * invL;
            *(float4*)(aptr + kc)     = p0;      // normalized attention out
            *(float4*)(aptr + kc + 4) = p1;
            uint4 hh, ll;
            split2(p0.x, p0.y, hh.x, ll.x);
            split2(p0.z, p0.w, hh.y, ll.y);
            split2(p1.x, p1.y, hh.z, ll.z);
            split2(p1.z, p1.w, hh.w, ll.w);
            asm volatile("st.shared.v4.b32 [%0], {%1,%2,%3,%4};\n"
                         :: "r"(dst), "r"(hh.x), "r"(hh.y), "r"(hh.z), "r"(hh.w));
            asm volatile("st.shared.v4.b32 [%0], {%1,%2,%3,%4};\n"
                         :: "r"(dst + 10240), "r"(ll.x), "r"(ll.y), "r"(ll.z), "r"(ll.w));
        } else {
            asm volatile("st.shared.v4.b32 [%0], {%1,%1,%1,%1};\n" :: "r"(dst), "r"(0u));
            asm volatile("st.shared.v4.b32 [%0], {%1,%1,%1,%1};\n" :: "r"(dst + 10240), "r"(0u));
        }
    };
    auto loadB = [&](int kc, uint32_t stg) {
        #pragma unroll
        for (int i = 0; i < 4; i++) {       // 32 k-rows x 256 b16 x 2 halves
            int u = tid + i * 512;
            int half = u >> 10, v = u & 1023, row = v >> 5, ch = v & 31;
            const __nv_bfloat16* src =
                (half ? g_xl : g_xh) + xoff + (size_t)(kc + row) * D_ + ch * 8;
            cp16(sb + stg + (uint32_t)(20480 + half * 16896 + row * 528 + ch * 16), src);
        }
        cp_commit();
    };

    float4 f0, f1;
    // prologue: stage 0 fully prepared
    ldgA(0, f0, f1);
    loadB(0, 0);
    procA(0, 0, f0, f1);

    #pragma unroll 1
    for (int c = 0; c < 128; c++) {
        if (c < 127) {
            ldgA((c + 1) * 32, f0, f1);                       // hidden under mma(c)
            loadB((c + 1) * 32, (uint32_t)(((c + 1) & 1) * G2_STAGE));
            cp_wait1();
        } else cp_wait0();
        __syncthreads();
        const uint32_t stg = sb + (uint32_t)((c & 1) * G2_STAGE);
        #pragma unroll
        for (int ks = 0; ks < 2; ks++) {
            uint32_t Ah[2][4], Al[2][4], Bh[4][4], Bl[4][4];
            #pragma unroll
            for (int mi = 0; mi < 2; mi++) {
                uint32_t a = stg + (uint32_t)(wm + 16 * mi + a_row) * 80 + (a_col + ks * 16) * 2;
                ldsm_x4(Ah[mi], a);
                ldsm_x4(Al[mi], a + 10240);
            }
            #pragma unroll
            for (int jj = 0; jj < 4; jj++) {
                uint32_t krow = (uint32_t)(ks * 16) + b_k8;
                uint32_t ncol = (uint32_t)(wn + (2 * jj + b_hi) * 8);
                uint32_t a = stg + 20480 + krow * 528 + ncol * 2;
                ldsm_x4_t(Bh[jj], a);
                ldsm_x4_t(Bl[jj], a + 16896);
            }
            #pragma unroll
            for (int mi = 0; mi < 2; mi++)
                #pragma unroll
                for (int nj = 0; nj < 8; nj++) {
                    int jp = nj >> 1, s2 = (nj & 1) * 2;
                    mma_bf16(acc[mi][nj], Ah[mi], Bh[jp][s2], Bh[jp][s2 + 1]);
                    mma_bf16(acc[mi][nj], Ah[mi], Bl[jp][s2], Bl[jp][s2 + 1]);
                    mma_bf16(acc[mi][nj], Al[mi], Bh[jp][s2], Bh[jp][s2 + 1]);
                }
        }
        if (c < 127) procA((c + 1) * 32, (uint32_t)(((c + 1) & 1) * G2_STAGE), f0, f1);
        __syncthreads();
    }

    float* outb = logits + (size_t)b * C_ * D_;
    #pragma unroll
    for (int mi = 0; mi < 2; mi++) {
        int c0 = m0 + wm + 16 * mi + (lane >> 2);
        #pragma unroll
        for (int nj = 0; nj < 8; nj++) {
            int d = wn + 8 * nj + (lane & 3) * 2;
            if (c0 < C_)
                *(float2*)(outb + (size_t)c0 * D_ + d) = make_float2(acc[mi][nj][0], acc[mi][nj][1]);
            if (c0 + 8 < C_)
                *(float2*)(outb + (size_t)(c0 + 8) * D_ + d) = make_float2(acc[mi][nj][2], acc[mi][nj][3]);
        }
    }
}

// ---------------------------------------------------------------------------
extern "C" void kernel_launch(void* const* d_in, const int* in_sizes, int n_in,
                              void* d_out, int out_size)
{
    const float* x = (const float*)d_in[0];   // [B, S, D]
    const float* W = (const float*)d_in[1];   // [C, D]

    float* logits = (float*)d_out;                            // [B, C, D]
    float* attn   = (float*)d_out + (size_t)B_ * C_ * D_;     // [B, C, S]

    cudaFuncSetAttribute(gemm1_k, cudaFuncAttributeMaxDynamicSharedMemorySize, 2 * G1_STAGE);
    cudaFuncSetAttribute(gemm2_k, cudaFuncAttributeMaxDynamicSharedMemorySize, 2 * G2_STAGE);

    __nv_bfloat16 *p_wh, *p_wl, *p_xh, *p_xl;
    cudaGetSymbolAddress((void**)&p_wh, g_wh);
    cudaGetSymbolAddress((void**)&p_wl, g_wl);
    cudaGetSymbolAddress((void**)&p_xh, g_xh);
    cudaGetSymbolAddress((void**)&p_xl, g_xl);

    const int nw4 = C_ * D_ / 4;
    const int nx4 = B_ * S_ * D_ / 4;
    split_kernel<<<(nw4 + 255) / 256, 256>>>(W, p_wh, p_wl, nw4);
    split_kernel<<<(nx4 + 255) / 256, 256>>>(x, p_xh, p_xl, nx4);

    gemm1_k<<<dim3(NSB, CTILES, B_), 256, 2 * G1_STAGE>>>(attn);

    rstats_k<<<(B_ * C_ + 255) / 256, 256>>>();

    gemm2_k<<<dim3(1, CTILES, B_), 512, 2 * G2_STAGE>>>(attn, logits);
}

// round 11
// speedup vs baseline: 2.8333x; 1.0009x over previous
#include <cuda_runtime.h>
#include <cuda_bf16.h>
#include <cstdint>

// LabelwiseAttention: B=4, S=4096, D=256, C=8921
//   scores[b,c,s] = sum_d x[b,s,d] * W[c,d]
//   attn          = softmax_s(scores)
//   logits[b,c,d] = sum_s attn[b,c,s] * x[b,s,d]
// d_out = [logits (B*C*D) | attention (B*C*S)], fp32.
//
// bf16 hi/lo split mma.sync (3 terms: hh, hl, lh), cp.async double-buffered.
// Softmax fused: gemm1 epilogue emits per-(row, s-block) (max, sumexp)
// partials; rstats combines; gemm2's A-loader exp/normalizes raw scores
// in d_out in place and feeds bf16 hi/lo fragments to the tensor cores.
// MMA issue order: term-outermost so consecutive mmas hit different
// accumulators (kills accumulator RAW chains).

#define B_ 4
#define S_ 4096
#define D_ 256
#define C_ 8921
#define CPAD 9088
#define CTILES 70        // ceil(C/128)
#define NSB 32           // s-blocks in gemm1 (S/128)

// ---- scratch ---------------------------------------------------------------
__device__ __nv_bfloat16 g_wh[(size_t)CPAD * D_];
__device__ __nv_bfloat16 g_wl[(size_t)CPAD * D_];
__device__ __nv_bfloat16 g_xh[(size_t)B_ * S_ * D_];
__device__ __nv_bfloat16 g_xl[(size_t)B_ * S_ * D_];
__device__ float2 g_part[(size_t)B_ * CPAD * NSB];   // per (row, s-block) (m, l)
__device__ float2 g_stats[(size_t)B_ * CPAD];        // per row (M, 1/L)

// ---- helpers ---------------------------------------------------------------
__device__ __forceinline__ uint32_t smem_u32(const void* p) {
    uint32_t a;
    asm("{ .reg .u64 t; cvta.to.shared.u64 t, %1; cvt.u32.u64 %0, t; }" : "=r"(a) : "l"(p));
    return a;
}
__device__ __forceinline__ void cp16(uint32_t dst, const void* src) {
    size_t g;
    asm("cvta.to.global.u64 %0, %1;" : "=l"(g) : "l"(src));
    asm volatile("cp.async.cg.shared.global [%0], [%1], 16;\n" :: "r"(dst), "l"(g));
}
__device__ __forceinline__ void cp_commit() { asm volatile("cp.async.commit_group;\n" ::: "memory"); }
__device__ __forceinline__ void cp_wait0()  { asm volatile("cp.async.wait_group 0;\n" ::: "memory"); }
__device__ __forceinline__ void cp_wait1()  { asm volatile("cp.async.wait_group 1;\n" ::: "memory"); }
__device__ __forceinline__ void ldsm_x4(uint32_t* r, uint32_t addr) {
    asm volatile("ldmatrix.sync.aligned.m8n8.x4.shared.b16 {%0,%1,%2,%3}, [%4];\n"
                 : "=r"(r[0]), "=r"(r[1]), "=r"(r[2]), "=r"(r[3]) : "r"(addr));
}
__device__ __forceinline__ void ldsm_x4_t(uint32_t* r, uint32_t addr) {
    asm volatile("ldmatrix.sync.aligned.m8n8.x4.trans.shared.b16 {%0,%1,%2,%3}, [%4];\n"
                 : "=r"(r[0]), "=r"(r[1]), "=r"(r[2]), "=r"(r[3]) : "r"(addr));
}
__device__ __forceinline__ void mma_bf16(float* c, const uint32_t* a, uint32_t b0, uint32_t b1) {
    asm volatile(
        "mma.sync.aligned.m16n8k16.row.col.f32.bf16.bf16.f32 "
        "{%0,%1,%2,%3}, {%4,%5,%6,%7}, {%8,%9}, {%0,%1,%2,%3};\n"
        : "+f"(c[0]), "+f"(c[1]), "+f"(c[2]), "+f"(c[3])
        : "r"(a[0]), "r"(a[1]), "r"(a[2]), "r"(a[3]), "r"(b0), "r"(b1));
}
__device__ __forceinline__ void split2(float a, float b, uint32_t& h, uint32_t& l) {
    __nv_bfloat16 ha = __float2bfloat16_rn(a), hb = __float2bfloat16_rn(b);
    __nv_bfloat16 la = __float2bfloat16_rn(a - __bfloat162float(ha));
    __nv_bfloat16 lb = __float2bfloat16_rn(b - __bfloat162float(hb));
    __nv_bfloat162 hh = __halves2bfloat162(ha, hb), ll = __halves2bfloat162(la, lb);
    h = *reinterpret_cast<uint32_t*>(&hh);
    l = *reinterpret_cast<uint32_t*>(&ll);
}

// ---- input split -----------------------------------------------------------
__global__ __launch_bounds__(256) void split_kernel(
    const float* __restrict__ src, __nv_bfloat16* __restrict__ dh,
    __nv_bfloat16* __restrict__ dl, int n4)
{
    int i = blockIdx.x * 256 + threadIdx.x;
    if (i >= n4) return;
    float4 v = ((const float4*)src)[i];
    uint32_t h0, l0, h1, l1;
    split2(v.x, v.y, h0, l0);
    split2(v.z, v.w, h1, l1);
    ((uint2*)dh)[i] = make_uint2(h0, h1);
    ((uint2*)dl)[i] = make_uint2(l0, l1);
}

// ---- GEMM1: scores = W . x^T; block 128(c) x 128(s), k-chunk 32 ------------
// stage (bytes): Ah[128 rows x 80B] @0 (10240), Al @10240, Bh @20480, Bl @30720
#define G1_STAGE 40960
__global__ __launch_bounds__(256, 2) void gemm1_k(float* __restrict__ scores)
{
    extern __shared__ char smem[];
    const uint32_t sb = smem_u32(smem);
    const int tid = threadIdx.x, lane = tid & 31, wid = tid >> 5;
    const int b = blockIdx.z, m0 = blockIdx.y * 128, n0 = blockIdx.x * 128;
    const int wm = (wid >> 2) * 64, wn = (wid & 3) * 32;
    const size_t xoff = (size_t)b * S_ * D_;

    float acc[4][4][4];
    #pragma unroll
    for (int i = 0; i < 4; i++)
        #pragma unroll
        for (int j = 0; j < 4; j++)
            #pragma unroll
            for (int k = 0; k < 4; k++) acc[i][j][k] = 0.f;

    const uint32_t a_row = (uint32_t)(lane & 15), a_col = (uint32_t)((lane >> 4) * 8);
    const uint32_t b_sub = (uint32_t)(((lane >> 3) & 1) * 8);
    const uint32_t b_lo  = (uint32_t)(lane & 7), b_hi = (uint32_t)(lane >> 4);

    auto load_stage = [&](int kc, uint32_t stg) {
        #pragma unroll
        for (int i = 0; i < 4; i++) {   // A: 128 rows x 32 b16 x 2 halves
            int u = tid + i * 256;
            int row = u >> 3, half = (u >> 2) & 1, ch = u & 3;
            const __nv_bfloat16* src =
                (half ? g_wl : g_wh) + (size_t)(m0 + row) * D_ + kc + ch * 8;
            cp16(sb + stg + (uint32_t)(half * 10240 + row * 80 + ch * 16), src);
        }
        #pragma unroll
        for (int i = 0; i < 4; i++) {   // B: 128 rows (s) x 32 b16 x 2 halves
            int u = tid + i * 256;
            int row = u >> 3, half = (u >> 2) & 1, ch = u & 3;
            const __nv_bfloat16* src =
                (half ? g_xl : g_xh) + xoff + (size_t)(n0 + row) * D_ + kc + ch * 8;
            cp16(sb + stg + (uint32_t)(20480 + half * 10240 + row * 80 + ch * 16), src);
        }
        cp_commit();
    };

    load_stage(0, 0);
    #pragma unroll 1
    for (int c = 0; c < 8; c++) {
        if (c < 7) { load_stage((c + 1) * 32, (uint32_t)(((c + 1) & 1) * G1_STAGE)); cp_wait1(); }
        else cp_wait0();
        __syncthreads();
        const uint32_t stg = sb + (uint32_t)((c & 1) * G1_STAGE);
        #pragma unroll
        for (int ks = 0; ks < 2; ks++) {
            uint32_t Ah[4][4], Al[4][4], Bh[2][4], Bl[2][4];
            #pragma unroll
            for (int mi = 0; mi < 4; mi++) {
                uint32_t a = stg + (uint32_t)(wm + 16 * mi + a_row) * 80 + (a_col + ks * 16) * 2;
                ldsm_x4(Ah[mi], a);
                ldsm_x4(Al[mi], a + 10240);
            }
            #pragma unroll
            for (int jj = 0; jj < 2; jj++) {
                uint32_t nrow = (uint32_t)(wn + (2 * jj + b_hi) * 8 + b_lo);
                uint32_t a = stg + 20480 + nrow * 80 + (b_sub + ks * 16) * 2;
                ldsm_x4(Bh[jj], a);
                ldsm_x4(Bl[jj], a + 10240);
            }
            // term-outermost: consecutive mmas hit different accumulators
            #pragma unroll
            for (int mi = 0; mi < 4; mi++)
                #pragma unroll
                for (int nj = 0; nj < 4; nj++)
                    mma_bf16(acc[mi][nj], Ah[mi], Bh[nj >> 1][(nj & 1) * 2], Bh[nj >> 1][(nj & 1) * 2 + 1]);
            #pragma unroll
            for (int mi = 0; mi < 4; mi++)
                #pragma unroll
                for (int nj = 0; nj < 4; nj++)
                    mma_bf16(acc[mi][nj], Ah[mi], Bl[nj >> 1][(nj & 1) * 2], Bl[nj >> 1][(nj & 1) * 2 + 1]);
            #pragma unroll
            for (int mi = 0; mi < 4; mi++)
                #pragma unroll
                for (int nj = 0; nj < 4; nj++)
                    mma_bf16(acc[mi][nj], Al[mi], Bh[nj >> 1][(nj & 1) * 2], Bh[nj >> 1][(nj & 1) * 2 + 1]);
        }
        __syncthreads();
    }

    // raw scores -> d_out attention region
    float* outb = scores + (size_t)b * C_ * S_;
    #pragma unroll
    for (int mi = 0; mi < 4; mi++) {
        int c0 = m0 + wm + 16 * mi + (lane >> 2);
        #pragma unroll
        for (int nj = 0; nj < 4; nj++) {
            int s = n0 + wn + 8 * nj + (lane & 3) * 2;
            if (c0 < C_)
                *(float2*)(outb + (size_t)c0 * S_ + s) = make_float2(acc[mi][nj][0], acc[mi][nj][1]);
            if (c0 + 8 < C_)
                *(float2*)(outb + (size_t)(c0 + 8) * S_ + s) = make_float2(acc[mi][nj][2], acc[mi][nj][3]);
        }
    }

    // --- per-row softmax partials over this 128-col s-block ---
    __syncthreads();                       // safe to reuse stage smem
    float* sm_m = (float*)smem;            // [128][4]
    float* sm_f = (float*)smem + 512;      // [128]
    float* sm_l = (float*)smem + 640;      // [128][4]

    #pragma unroll
    for (int mi = 0; mi < 4; mi++)
        #pragma unroll
        for (int h = 0; h < 2; h++) {
            int r = wm + 16 * mi + (lane >> 2) + 8 * h;
            float vm = -3.402823466e38f;
            #pragma unroll
            for (int nj = 0; nj < 4; nj++)
                vm = fmaxf(vm, fmaxf(acc[mi][nj][2 * h], acc[mi][nj][2 * h + 1]));
            vm = fmaxf(vm, __shfl_xor_sync(0xFFFFFFFFu, vm, 1));
            vm = fmaxf(vm, __shfl_xor_sync(0xFFFFFFFFu, vm, 2));
            if ((lane & 3) == 0) sm_m[r * 4 + (wid & 3)] = vm;
        }
    __syncthreads();
    if (tid < 128) {
        float m = fmaxf(fmaxf(sm_m[tid * 4], sm_m[tid * 4 + 1]),
                        fmaxf(sm_m[tid * 4 + 2], sm_m[tid * 4 + 3]));
        sm_f[tid] = m;
    }
    __syncthreads();
    #pragma unroll
    for (int mi = 0; mi < 4; mi++)
        #pragma unroll
        for (int h = 0; h < 2; h++) {
            int r = wm + 16 * mi + (lane >> 2) + 8 * h;
            float m = sm_f[r], ls = 0.f;
            #pragma unroll
            for (int nj = 0; nj < 4; nj++)
                ls += __expf(acc[mi][nj][2 * h] - m) + __expf(acc[mi][nj][2 * h + 1] - m);
            ls += __shfl_xor_sync(0xFFFFFFFFu, ls, 1);
            ls += __shfl_xor_sync(0xFFFFFFFFu, ls, 2);
            if ((lane & 3) == 0) sm_l[r * 4 + (wid & 3)] = ls;
        }
    __syncthreads();
    if (tid < 128) {
        int c = m0 + tid;
        if (c < C_) {
            float l = sm_l[tid * 4] + sm_l[tid * 4 + 1] + sm_l[tid * 4 + 2] + sm_l[tid * 4 + 3];
            g_part[((size_t)b * CPAD + c) * NSB + blockIdx.x] = make_float2(sm_f[tid], l);
        }
    }
}

// ---- rstats: combine NSB partials per row -> (M, 1/L) ----------------------
__global__ __launch_bounds__(256) void rstats_k()
{
    int idx = blockIdx.x * 256 + threadIdx.x;
    if (idx >= B_ * C_) return;
    int b = idx / C_, c = idx % C_;
    const float2* p = &g_part[((size_t)b * CPAD + c) * NSB];
    float M = -3.402823466e38f;
    #pragma unroll
    for (int i = 0; i < NSB; i++) M = fmaxf(M, p[i].x);
    float L = 0.f;
    #pragma unroll
    for (int i = 0; i < NSB; i++) L += p[i].y * __expf(p[i].x - M);
    g_stats[(size_t)b * CPAD + c] = make_float2(M, 1.0f / L);
}

// ---- GEMM2: logits = attn . x; block 128(c) x 256(d), 512 thr, k-chunk 32 --
// stage: Ah[128x80B] @0 (10240), Al @10240, Bh[32x528B] @20480 (16896), Bl @37376
#define G2_STAGE 54272
__global__ __launch_bounds__(512, 1) void gemm2_k(float* __restrict__ attn,
                                                  float* __restrict__ logits)
{
    extern __shared__ char smem[];
    const uint32_t sb = smem_u32(smem);
    const int tid = threadIdx.x, lane = tid & 31, wid = tid >> 5;
    const int b = blockIdx.z, m0 = blockIdx.y * 128;
    const int wm = (wid >> 2) * 32, wn = (wid & 3) * 64;
    const size_t xoff = (size_t)b * S_ * D_;

    float acc[2][8][4];
    #pragma unroll
    for (int i = 0; i < 2; i++)
        #pragma unroll
        for (int j = 0; j < 8; j++)
            #pragma unroll
            for (int k = 0; k < 4; k++) acc[i][j][k] = 0.f;

    const uint32_t a_row = (uint32_t)(lane & 15), a_col = (uint32_t)((lane >> 4) * 8);
    const uint32_t b_k8  = (uint32_t)(((lane >> 3) & 1) * 8 + (lane & 7));
    const uint32_t b_hi  = (uint32_t)(lane >> 4);

    // A-loader mapping: each thread owns one score row, 8 fp32 per chunk
    const int arow = tid >> 2;               // 0..127
    const int acg  = (tid & 3) * 8;          // col group within chunk
    const int cglob = m0 + arow;
    const bool avalid = cglob < C_;
    float* aptr = attn + ((size_t)b * C_ + cglob) * S_ + acg;   // valid only if avalid
    float M = 0.f, invL = 0.f;
    if (avalid) {
        float2 st = g_stats[(size_t)b * CPAD + cglob];
        M = st.x; invL = st.y;
    }

    auto ldgA = [&](int kc, float4& f0, float4& f1) {
        if (avalid) {
            f0 = *(const float4*)(aptr + kc);
            f1 = *(const float4*)(aptr + kc + 4);
        }
    };
    auto procA = [&](int kc, uint32_t stg, float4 f0, float4 f1) {
        uint32_t dst = sb + stg + (uint32_t)(arow * 80 + acg * 2);
        if (avalid) {
            float4 p0, p1;
            p0.x = __expf(f0.x - M) * invL; p0.y = __expf(f0.y - M) * invL;
            p0.z = __expf(f0.z - M) * invL; p0.w = __expf(f0.w - M) * invL;
            p1.x = __expf(f1.x - M) * invL; p1.y = __expf(f1.y - M) * invL;
            p1.z = __expf(f1.z - M) * invL; p1.w = __expf(f1.w - M) * invL;
            *(float4*)(aptr + kc)     = p0;      // normalized attention out
            *(float4*)(aptr + kc + 4) = p1;
            uint4 hh, ll;
            split2(p0.x, p0.y, hh.x, ll.x);
            split2(p0.z, p0.w, hh.y, ll.y);
            split2(p1.x, p1.y, hh.z, ll.z);
            split2(p1.z, p1.w, hh.w, ll.w);
            asm volatile("st.shared.v4.b32 [%0], {%1,%2,%3,%4};\n"
                         :: "r"(dst), "r"(hh.x), "r"(hh.y), "r"(hh.z), "r"(hh.w));
            asm volatile("st.shared.v4.b32 [%0], {%1,%2,%3,%4};\n"
                         :: "r"(dst + 10240), "r"(ll.x), "r"(ll.y), "r"(ll.z), "r"(ll.w));
        } else {
            asm volatile("st.shared.v4.b32 [%0], {%1,%1,%1,%1};\n" :: "r"(dst), "r"(0u));
            asm volatile("st.shared.v4.b32 [%0], {%1,%1,%1,%1};\n" :: "r"(dst + 10240), "r"(0u));
        }
    };
    auto loadB = [&](int kc, uint32_t stg) {
        #pragma unroll
        for (int i = 0; i < 4; i++) {       // 32 k-rows x 256 b16 x 2 halves
            int u = tid + i * 512;
            int half = u >> 10, v = u & 1023, row = v >> 5, ch = v & 31;
            const __nv_bfloat16* src =
                (half ? g_xl : g_xh) + xoff + (size_t)(kc + row) * D_ + ch * 8;
            cp16(sb + stg + (uint32_t)(20480 + half * 16896 + row * 528 + ch * 16), src);
        }
        cp_commit();
    };

    float4 f0, f1;
    // prologue: stage 0 fully prepared
    ldgA(0, f0, f1);
    loadB(0, 0);
    procA(0, 0, f0, f1);

    #pragma unroll 1
    for (int c = 0; c < 128; c++) {
        if (c < 127) {
            ldgA((c + 1) * 32, f0, f1);                       // hidden under mma(c)
            loadB((c + 1) * 32, (uint32_t)(((c + 1) & 1) * G2_STAGE));
            cp_wait1();
        } else cp_wait0();
        __syncthreads();
        const uint32_t stg = sb + (uint32_t)((c & 1) * G2_STAGE);
        #pragma unroll
        for (int ks = 0; ks < 2; ks++) {
            uint32_t Ah[2][4], Al[2][4], Bh[4][4], Bl[4][4];
            #pragma unroll
            for (int mi = 0; mi < 2; mi++) {
                uint32_t a = stg + (uint32_t)(wm + 16 * mi + a_row) * 80 + (a_col + ks * 16) * 2;
                ldsm_x4(Ah[mi], a);
                ldsm_x4(Al[mi], a + 10240);
            }
            #pragma unroll
            for (int jj = 0; jj < 4; jj++) {
                uint32_t krow = (uint32_t)(ks * 16) + b_k8;
                uint32_t ncol = (uint32_t)(wn + (2 * jj + b_hi) * 8);
                uint32_t a = stg + 20480 + krow * 528 + ncol * 2;
                ldsm_x4_t(Bh[jj], a);
                ldsm_x4_t(Bl[jj], a + 16896);
            }
            // term-outermost: consecutive mmas hit different accumulators
            #pragma unroll
            for (int mi = 0; mi < 2; mi++)
                #pragma unroll
                for (int nj = 0; nj < 8; nj++)
                    mma_bf16(acc[mi][nj], Ah[mi], Bh[nj >> 1][(nj & 1) * 2], Bh[nj >> 1][(nj & 1) * 2 + 1]);
            #pragma unroll
            for (int mi = 0; mi < 2; mi++)
                #pragma unroll
                for (int nj = 0; nj < 8; nj++)
                    mma_bf16(acc[mi][nj], Ah[mi], Bl[nj >> 1][(nj & 1) * 2], Bl[nj >> 1][(nj & 1) * 2 + 1]);
            #pragma unroll
            for (int mi = 0; mi < 2; mi++)
                #pragma unroll
                for (int nj = 0; nj < 8; nj++)
                    mma_bf16(acc[mi][nj], Al[mi], Bh[nj >> 1][(nj & 1) * 2], Bh[nj >> 1][(nj & 1) * 2 + 1]);
        }
        if (c < 127) procA((c + 1) * 32, (uint32_t)(((c + 1) & 1) * G2_STAGE), f0, f1);
        __syncthreads();
    }

    float* outb = logits + (size_t)b * C_ * D_;
    #pragma unroll
    for (int mi = 0; mi < 2; mi++) {
        int c0 = m0 + wm + 16 * mi + (lane >> 2);
        #pragma unroll
        for (int nj = 0; nj < 8; nj++) {
            int d = wn + 8 * nj + (lane & 3) * 2;
            if (c0 < C_)
                *(float2*)(outb + (size_t)c0 * D_ + d) = make_float2(acc[mi][nj][0], acc[mi][nj][1]);
            if (c0 + 8 < C_)
                *(float2*)(outb + (size_t)(c0 + 8) * D_ + d) = make_float2(acc[mi][nj][2], acc[mi][nj][3]);
        }
    }
}

// ---------------------------------------------------------------------------
extern "C" void kernel_launch(void* const* d_in, const int* in_sizes, int n_in,
                              void* d_out, int out_size)
{
    const float* x = (const float*)d_in[0];   // [B, S, D]
    const float* W = (const float*)d_in[1];   // [C, D]

    float* logits = (float*)d_out;                            // [B, C, D]
    float* attn   = (float*)d_out + (size_t)B_ * C_ * D_;     // [B, C, S]

    cudaFuncSetAttribute(gemm1_k, cudaFuncAttributeMaxDynamicSharedMemorySize, 2 * G1_STAGE);
    cudaFuncSetAttribute(gemm2_k, cudaFuncAttributeMaxDynamicSharedMemorySize, 2 * G2_STAGE);

    __nv_bfloat16 *p_wh, *p_wl, *p_xh, *p_xl;
    cudaGetSymbolAddress((void**)&p_wh, g_wh);
    cudaGetSymbolAddress((void**)&p_wl, g_wl);
    cudaGetSymbolAddress((void**)&p_xh, g_xh);
    cudaGetSymbolAddress((void**)&p_xl, g_xl);

    const int nw4 = C_ * D_ / 4;
    const int nx4 = B_ * S_ * D_ / 4;
    split_kernel<<<(nw4 + 255) / 256, 256>>>(W, p_wh, p_wl, nw4);
    split_kernel<<<(nx4 + 255) / 256, 256>>>(x, p_xh, p_xl, nx4);

    gemm1_k<<<dim3(NSB, CTILES, B_), 256, 2 * G1_STAGE>>>(attn);

    rstats_k<<<(B_ * C_ + 255) / 256, 256>>>();

    gemm2_k<<<dim3(1, CTILES, B_), 512, 2 * G2_STAGE>>>(attn, logits);
}